// round 8
// baseline (speedup 1.0000x reference)
#include <cuda_runtime.h>
#include <cuda_fp16.h>

// SpatialTransformer3D: batched 3D trilinear sampling.
//
// Prepass packs the image into fp16 x-pair patches, 2 parity copies:
//   patch(b,sx,y,px,z) = { img[y, 2px+sx, z], img[y, min(2px+sx+1,127), z] }
//   = 8 halves = 16B. Total packed = 67MB.
// Main kernel: 2 lanes per voxel (lane bit0 = z-corner), 4 voxels per thread
// (quad shares b,i,j) -> 8 independent 16B gathers in flight per thread.
// Pair lanes' patches at z0/z0+1 are 16B apart -> same 128B line.
// Per voxel: y0-patch + y1-patch = 2 distinct lines.
//
// image: (B=2, H=128, W=128, D=128, C=4) f32
// transformation: (B=2, 128, 128, 128, 3) f32
// out: (B=2, 128, 128, 128, 4) f32

__device__ uint4 g_packed[4 * 1048576];   // (b,sx) x (y,px,z) = 67MB

__device__ __forceinline__ unsigned pack2(float a, float b) {
    __half2 h = __floats2half2_rn(a, b);
    return *reinterpret_cast<unsigned*>(&h);
}
__device__ __forceinline__ float2 up2(unsigned u) {
    __half2 h = *reinterpret_cast<__half2*>(&u);
    return __half22float2(h);
}

// one block per (b,y,px); 128 threads = z
__global__ __launch_bounds__(128) void repack_kernel(const float4* __restrict__ img)
{
    int z  = threadIdx.x;
    int bk = blockIdx.x;
    int px = bk & 63;
    int y  = (bk >> 6) & 127;
    int b  = bk >> 13;

    const float4* imgb = img + (size_t)b * 2097152;
    int x0 = 2 * px;

    float4 v0 = __ldg(&imgb[(y << 14) | (x0 << 7) | z]);
    float4 v1 = __ldg(&imgb[(y << 14) | ((x0 + 1) << 7) | z]);
    float4 v2 = __ldg(&imgb[(y << 14) | (min(x0 + 2, 127) << 7) | z]);

    uint4 H0, H1;
    H0.x = pack2(v0.x, v0.y);  H0.y = pack2(v0.z, v0.w);
    H0.z = pack2(v1.x, v1.y);  H0.w = pack2(v1.z, v1.w);
    H1.x = pack2(v1.x, v1.y);  H1.y = pack2(v1.z, v1.w);
    H1.z = pack2(v2.x, v2.y);  H1.w = pack2(v2.z, v2.w);

    int base = (y << 13) | (px << 7) | z;
    g_packed[(((b << 1) | 0) << 20) | base] = H0;
    g_packed[(((b << 1) | 1) << 20) | base] = H1;
}

struct VSetup {
    int   base;    // packed index without y bits
    int   y0, y1;
    float dx, dy, wz;
};

__device__ __forceinline__ VSetup vsetup(float tx, float ty, float tz,
                                         float xl, float yl, float zl,
                                         int b, int hs)
{
    VSetup s;
    float x = 0.5f * (tx * xl + 1.0f) * 128.0f;
    float y = 0.5f * (ty * yl + 1.0f) * 128.0f;
    float z = 0.5f * (tz * zl + 1.0f) * 128.0f;

    int x0 = min(max((int)floorf(x), 0), 127);
    int y0 = (int)floorf(y);
    int z0 = min(max((int)floorf(z), 0), 127);
    int x1 = min(x0 + 1, 127);
    int y1 = min(max(y0 + 1, 0), 127);
    int z1 = min(z0 + 1, 127);
    y0 = min(max(y0, 0), 127);

    float dz = (float)z1 - z;
    s.dx = (float)x1 - x;
    s.dy = (float)y1 - y;
    s.wz = hs ? (1.0f - dz) : dz;
    s.y0 = y0;
    s.y1 = y1;
    int zi = hs ? z1 : z0;
    s.base = (((b << 1) | (x0 & 1)) << 20) | ((x0 >> 1) << 7) | zi;
    return s;
}

__device__ __forceinline__ float4 vblend(const uint4& h0, const uint4& h1,
                                         const VSetup& s)
{
    float wy0 = s.wz * s.dy, wy1 = s.wz * (1.0f - s.dy);
    float dx = s.dx, ex = 1.0f - s.dx;

    float2 a0c01 = up2(h0.x), a0c23 = up2(h0.y);  // y0: x0 voxel
    float2 a1c01 = up2(h0.z), a1c23 = up2(h0.w);  // y0: x1 voxel
    float2 b0c01 = up2(h1.x), b0c23 = up2(h1.y);  // y1: x0 voxel
    float2 b1c01 = up2(h1.z), b1c23 = up2(h1.w);  // y1: x1 voxel

    float4 r;
    r.x = wy0 * (dx * a0c01.x + ex * a1c01.x) + wy1 * (dx * b0c01.x + ex * b1c01.x);
    r.y = wy0 * (dx * a0c01.y + ex * a1c01.y) + wy1 * (dx * b0c01.y + ex * b1c01.y);
    r.z = wy0 * (dx * a0c23.x + ex * a1c23.x) + wy1 * (dx * b0c23.x + ex * b1c23.x);
    r.w = wy0 * (dx * a0c23.y + ex * a1c23.y) + wy1 * (dx * b0c23.y + ex * b1c23.y);
    return r;
}

__device__ __forceinline__ void bfly4(float4& r) {
    r.x += __shfl_xor_sync(0xffffffffu, r.x, 1);
    r.y += __shfl_xor_sync(0xffffffffu, r.y, 1);
    r.z += __shfl_xor_sync(0xffffffffu, r.z, 1);
    r.w += __shfl_xor_sync(0xffffffffu, r.w, 1);
}

__global__ __launch_bounds__(256) void st3d_kernel(
    const float* __restrict__ trans,
    float* __restrict__ out)
{
    int t = blockIdx.x * blockDim.x + threadIdx.x;

    int hs = t & 1;          // z-corner select: 0 -> z0, 1 -> z1
    int q  = t >> 1;         // quad index: voxels v0 = 4q .. 4q+3
    int v0 = q << 2;

    // v0 = ((b*128 + i)*128 + j)*128 + k0, k0 = 0 mod 4 -> quad shares b,i,j
    int k0 = v0 & 127;
    int j  = (v0 >> 7) & 127;
    int i  = (v0 >> 14) & 127;
    int b  = v0 >> 21;

    const float step = 2.0f / 127.0f;
    float xl  = -1.0f + (float)j * step;
    float yl  = -1.0f + (float)i * step;
    float zl0 = -1.0f + (float)k0 * step;

    // 12 transform floats for the quad: 48 contiguous bytes, 16B-aligned
    const float4* tq = reinterpret_cast<const float4*>(trans) + (size_t)q * 3;
    float4 f0 = __ldg(&tq[0]);   // txA tyA tzA txB
    float4 f1 = __ldg(&tq[1]);   // tyB tzB txC tyC
    float4 f2 = __ldg(&tq[2]);   // tzC txD tyD tzD

    VSetup sA = vsetup(f0.x, f0.y, f0.z, xl, yl, zl0,            b, hs);
    VSetup sB = vsetup(f0.w, f1.x, f1.y, xl, yl, zl0 + step,     b, hs);
    VSetup sC = vsetup(f1.z, f1.w, f2.x, xl, yl, zl0 + 2*step,   b, hs);
    VSetup sD = vsetup(f2.y, f2.z, f2.w, xl, yl, zl0 + 3*step,   b, hs);

    // ---- issue all 8 gathers back-to-back (pair lanes share lines) ----
    uint4 hA0 = g_packed[sA.base | (sA.y0 << 13)];
    uint4 hA1 = g_packed[sA.base | (sA.y1 << 13)];
    uint4 hB0 = g_packed[sB.base | (sB.y0 << 13)];
    uint4 hB1 = g_packed[sB.base | (sB.y1 << 13)];
    uint4 hC0 = g_packed[sC.base | (sC.y0 << 13)];
    uint4 hC1 = g_packed[sC.base | (sC.y1 << 13)];
    uint4 hD0 = g_packed[sD.base | (sD.y0 << 13)];
    uint4 hD1 = g_packed[sD.base | (sD.y1 << 13)];

    float4 rA = vblend(hA0, hA1, sA);
    float4 rB = vblend(hB0, hB1, sB);
    float4 rC = vblend(hC0, hC1, sC);
    float4 rD = vblend(hD0, hD1, sD);

    bfly4(rA); bfly4(rB); bfly4(rC); bfly4(rD);

    // even lane stores v0, v0+1; odd lane stores v0+2, v0+3
    float4* o = reinterpret_cast<float4*>(out) + v0 + (hs << 1);
    o[0] = hs ? rC : rA;
    o[1] = hs ? rD : rB;
}

extern "C" void kernel_launch(void* const* d_in, const int* in_sizes, int n_in,
                              void* d_out, int out_size)
{
    const float* img = (const float*)d_in[0];
    const float* trans = (const float*)d_in[1];
    float* out = (float*)d_out;

    // prepass: build 2 x-parity copies of fp16 x-pair patches (67MB)
    repack_kernel<<<2 * 128 * 64, 128>>>(reinterpret_cast<const float4*>(img));

    int total_threads = out_size / 8;  // 2 lanes x 4 voxels -> half of voxel count
    st3d_kernel<<<total_threads / 256, 256>>>(trans, out);
}

// round 9
// speedup vs baseline: 1.0287x; 1.0287x over previous
#include <cuda_runtime.h>
#include <cuda_fp16.h>

// SpatialTransformer3D: batched 3D trilinear sampling.
//
// Prepass packs the image into fp16 x-pair patches, 2 parity copies:
//   patch(b,sx,y,px,z) = { img[y, 2px+sx, z], img[y, min(2px+sx+1,127), z] }
//   = 8 halves = 16B. Total packed = 67MB (kept L2-resident; trans/out use
//   streaming cache hints to avoid evicting it).
// Main kernel (R7 structure): lane bit0 = z-corner select; pair lanes load
// patches at z0 / z0+1 (16B apart -> same 128B line). Per voxel:
// y0-patch + y1-patch = 2 distinct lines, ~96B of L2 sectors.
//
// image: (B=2, H=128, W=128, D=128, C=4) f32
// transformation: (B=2, 128, 128, 128, 3) f32
// out: (B=2, 128, 128, 128, 4) f32

__device__ uint4 g_packed[4 * 1048576];   // (b,sx) x (y,px,z), 67MB

__device__ __forceinline__ unsigned pack2(float a, float b) {
    __half2 h = __floats2half2_rn(a, b);
    return *reinterpret_cast<unsigned*>(&h);
}
__device__ __forceinline__ float2 up2(unsigned u) {
    __half2 h = *reinterpret_cast<__half2*>(&u);
    return __half22float2(h);
}

// grid: (b,y,quarter) = 1024 blocks; 128 threads = z. Register-carry over px:
// reads each img voxel ~once (coalesced), writes both parity patches.
__global__ __launch_bounds__(128) void repack_kernel(const float4* __restrict__ img)
{
    int z  = threadIdx.x;
    int bk = blockIdx.x;
    int qr = bk & 3;
    int y  = (bk >> 2) & 127;
    int b  = bk >> 9;

    const float4* imgb = img + (size_t)b * 2097152;
    int px0 = qr * 16;

    float4 prev = __ldg(&imgb[(y << 14) | ((2 * px0) << 7) | z]);  // v(2*px0)

#pragma unroll 4
    for (int px = px0; px < px0 + 16; ++px) {
        float4 v1 = __ldg(&imgb[(y << 14) | ((2 * px + 1) << 7) | z]);
        int x2 = min(2 * px + 2, 127);
        float4 v2 = __ldg(&imgb[(y << 14) | (x2 << 7) | z]);

        uint4 H0, H1;
        H0.x = pack2(prev.x, prev.y);  H0.y = pack2(prev.z, prev.w);
        H0.z = pack2(v1.x, v1.y);      H0.w = pack2(v1.z, v1.w);
        H1.x = pack2(v1.x, v1.y);      H1.y = pack2(v1.z, v1.w);
        H1.z = pack2(v2.x, v2.y);      H1.w = pack2(v2.z, v2.w);

        int base = (y << 13) | (px << 7) | z;
        g_packed[(((b << 1) | 0) << 20) | base] = H0;
        g_packed[(((b << 1) | 1) << 20) | base] = H1;

        prev = v2;
    }
}

__global__ __launch_bounds__(256) void st3d_kernel(
    const float* __restrict__ trans,
    float* __restrict__ out)
{
    int t = blockIdx.x * blockDim.x + threadIdx.x;

    int hs = t & 1;          // z-corner select: 0 -> z0, 1 -> z1
    int q  = t >> 1;         // voxel-pair index: voxels v0 = 2q, v0+1
    int v0 = q << 1;

    // v0 = ((b*128 + i)*128 + j)*128 + k0, k0 even -> pair shares b,i,j
    int k0 = v0 & 127;
    int j  = (v0 >> 7) & 127;
    int i  = (v0 >> 14) & 127;
    int b  = v0 >> 21;

    const float step = 2.0f / 127.0f;
    float xl  = -1.0f + (float)j * step;
    float yl  = -1.0f + (float)i * step;
    float zlA = -1.0f + (float)k0 * step;
    float zlB = zlA + step;

    // 6 transform floats for the voxel pair (streaming: don't pollute L2)
    const float2* tp = reinterpret_cast<const float2*>(trans) + (size_t)q * 3;
    float2 fa = __ldcs(&tp[0]);   // txA, tyA
    float2 fb = __ldcs(&tp[1]);   // tzA, txB
    float2 fc = __ldcs(&tp[2]);   // tyB, tzB

    // ---- voxel A setup ----
    float xA = 0.5f * (fa.x * xl + 1.0f) * 128.0f;
    float yA = 0.5f * (fa.y * yl + 1.0f) * 128.0f;
    float zA = 0.5f * (fb.x * zlA + 1.0f) * 128.0f;

    int x0A = min(max((int)floorf(xA), 0), 127);
    int y0A = (int)floorf(yA);
    int z0A = min(max((int)floorf(zA), 0), 127);
    int x1A = min(x0A + 1, 127);
    int y1A = min(max(y0A + 1, 0), 127);
    int z1A = min(z0A + 1, 127);
    y0A = min(max(y0A, 0), 127);

    float dxA = (float)x1A - xA, dyA = (float)y1A - yA, dzA = (float)z1A - zA;
    int   ziA = hs ? z1A : z0A;
    float wzA = hs ? (1.0f - dzA) : dzA;

    int baseA = (((b << 1) | (x0A & 1)) << 20) | ((x0A >> 1) << 7) | ziA;

    // ---- voxel B setup ----
    float xB = 0.5f * (fb.y * xl + 1.0f) * 128.0f;
    float yB = 0.5f * (fc.x * yl + 1.0f) * 128.0f;
    float zB = 0.5f * (fc.y * zlB + 1.0f) * 128.0f;

    int x0B = min(max((int)floorf(xB), 0), 127);
    int y0B = (int)floorf(yB);
    int z0B = min(max((int)floorf(zB), 0), 127);
    int x1B = min(x0B + 1, 127);
    int y1B = min(max(y0B + 1, 0), 127);
    int z1B = min(z0B + 1, 127);
    y0B = min(max(y0B, 0), 127);

    float dxB = (float)x1B - xB, dyB = (float)y1B - yB, dzB = (float)z1B - zB;
    int   ziB = hs ? z1B : z0B;
    float wzB = hs ? (1.0f - dzB) : dzB;

    int baseB = (((b << 1) | (x0B & 1)) << 20) | ((x0B >> 1) << 7) | ziB;

    // ---- issue all 4 gathers back-to-back (pair lanes share lines) ----
    uint4 hA0 = g_packed[baseA | (y0A << 13)];
    uint4 hA1 = g_packed[baseA | (y1A << 13)];
    uint4 hB0 = g_packed[baseB | (y0B << 13)];
    uint4 hB1 = g_packed[baseB | (y1B << 13)];

    float4 rA, rB;
    // ---- voxel A blend (this lane's z-corner) ----
    {
        float wy0 = wzA * dyA, wy1 = wzA * (1.0f - dyA);
        float ex  = 1.0f - dxA;

        float2 a0c01 = up2(hA0.x), a0c23 = up2(hA0.y);  // y0: x0 voxel
        float2 a1c01 = up2(hA0.z), a1c23 = up2(hA0.w);  // y0: x1 voxel
        float2 b0c01 = up2(hA1.x), b0c23 = up2(hA1.y);  // y1: x0 voxel
        float2 b1c01 = up2(hA1.z), b1c23 = up2(hA1.w);  // y1: x1 voxel

        rA.x = wy0 * (dxA * a0c01.x + ex * a1c01.x) + wy1 * (dxA * b0c01.x + ex * b1c01.x);
        rA.y = wy0 * (dxA * a0c01.y + ex * a1c01.y) + wy1 * (dxA * b0c01.y + ex * b1c01.y);
        rA.z = wy0 * (dxA * a0c23.x + ex * a1c23.x) + wy1 * (dxA * b0c23.x + ex * b1c23.x);
        rA.w = wy0 * (dxA * a0c23.y + ex * a1c23.y) + wy1 * (dxA * b0c23.y + ex * b1c23.y);
    }
    // ---- voxel B blend ----
    {
        float wy0 = wzB * dyB, wy1 = wzB * (1.0f - dyB);
        float ex  = 1.0f - dxB;

        float2 a0c01 = up2(hB0.x), a0c23 = up2(hB0.y);
        float2 a1c01 = up2(hB0.z), a1c23 = up2(hB0.w);
        float2 b0c01 = up2(hB1.x), b0c23 = up2(hB1.y);
        float2 b1c01 = up2(hB1.z), b1c23 = up2(hB1.w);

        rB.x = wy0 * (dxB * a0c01.x + ex * a1c01.x) + wy1 * (dxB * b0c01.x + ex * b1c01.x);
        rB.y = wy0 * (dxB * a0c01.y + ex * a1c01.y) + wy1 * (dxB * b0c01.y + ex * b1c01.y);
        rB.z = wy0 * (dxB * a0c23.x + ex * a1c23.x) + wy1 * (dxB * b0c23.x + ex * b1c23.x);
        rB.w = wy0 * (dxB * a0c23.y + ex * a1c23.y) + wy1 * (dxB * b0c23.y + ex * b1c23.y);
    }

    // combine z halves across the lane pair (both voxels)
    rA.x += __shfl_xor_sync(0xffffffffu, rA.x, 1);
    rA.y += __shfl_xor_sync(0xffffffffu, rA.y, 1);
    rA.z += __shfl_xor_sync(0xffffffffu, rA.z, 1);
    rA.w += __shfl_xor_sync(0xffffffffu, rA.w, 1);
    rB.x += __shfl_xor_sync(0xffffffffu, rB.x, 1);
    rB.y += __shfl_xor_sync(0xffffffffu, rB.y, 1);
    rB.z += __shfl_xor_sync(0xffffffffu, rB.z, 1);
    rB.w += __shfl_xor_sync(0xffffffffu, rB.w, 1);

    // even lane stores voxel v0, odd lane stores v0+1 -> dense streaming store
    float4 r = hs ? rB : rA;
    __stcs(reinterpret_cast<float4*>(out) + v0 + hs, r);
}

extern "C" void kernel_launch(void* const* d_in, const int* in_sizes, int n_in,
                              void* d_out, int out_size)
{
    const float* img = (const float*)d_in[0];
    const float* trans = (const float*)d_in[1];
    float* out = (float*)d_out;

    // prepass: 2 x-parity copies of fp16 x-pair patches (67MB), carry-loop reads
    repack_kernel<<<2 * 128 * 4, 128>>>(reinterpret_cast<const float4*>(img));

    int total_threads = out_size / 4;
    st3d_kernel<<<total_threads / 256, 256>>>(trans, out);
}

// round 10
// speedup vs baseline: 1.0894x; 1.0590x over previous
#include <cuda_runtime.h>
#include <cuda_fp16.h>

// SpatialTransformer3D: batched 3D trilinear sampling.
//
// Prepass packs the image into fp16 x-pair patches, 2 parity copies:
//   patch(b,sx,y,px,z) = { img[y, 2px+sx, z], img[y, min(2px+sx+1,127), z] }
//   = 8 halves = 16B. Packed total 67MB -> fits L2. Prepass reads img with
//   __ldcs (evict-first) so the dirty packed lines stay L2-resident for the
//   main kernel; writeback to DRAM overlaps the main kernel.
// Main kernel: lane bit0 = z-corner select; pair lanes load patches at
// z0 / z0+1 (16B apart -> same 128B line) -> 2 distinct lines per voxel.
// trans/out use streaming hints to avoid evicting packed from L2.
//
// image: (B=2, H=128, W=128, D=128, C=4) f32
// transformation: (B=2, 128, 128, 128, 3) f32
// out: (B=2, 128, 128, 128, 4) f32

__device__ uint4 g_packed[4 * 1048576];   // (b,sx) x (y,px,z), 67MB

__device__ __forceinline__ unsigned pack2(float a, float b) {
    __half2 h = __floats2half2_rn(a, b);
    return *reinterpret_cast<unsigned*>(&h);
}
__device__ __forceinline__ float2 up2(unsigned u) {
    __half2 h = *reinterpret_cast<__half2*>(&u);
    return __half22float2(h);
}

// one block per (b,y,px); 128 threads = z  (R7 structure: max parallelism)
__global__ __launch_bounds__(128) void repack_kernel(const float4* __restrict__ img)
{
    int z  = threadIdx.x;
    int bk = blockIdx.x;
    int px = bk & 63;
    int y  = (bk >> 6) & 127;
    int b  = bk >> 13;

    const float4* imgb = img + (size_t)b * 2097152;
    int x0 = 2 * px;

    // evict-first reads: don't let the f32 image displace packed in L2
    float4 v0 = __ldcs(&imgb[(y << 14) | (x0 << 7) | z]);
    float4 v1 = __ldcs(&imgb[(y << 14) | ((x0 + 1) << 7) | z]);
    float4 v2 = __ldcs(&imgb[(y << 14) | (min(x0 + 2, 127) << 7) | z]);

    uint4 H0, H1;
    H0.x = pack2(v0.x, v0.y);  H0.y = pack2(v0.z, v0.w);
    H0.z = pack2(v1.x, v1.y);  H0.w = pack2(v1.z, v1.w);
    H1.x = pack2(v1.x, v1.y);  H1.y = pack2(v1.z, v1.w);
    H1.z = pack2(v2.x, v2.y);  H1.w = pack2(v2.z, v2.w);

    int base = (y << 13) | (px << 7) | z;
    // default write-back stores: dirty lines stay resident in L2
    g_packed[(((b << 1) | 0) << 20) | base] = H0;
    g_packed[(((b << 1) | 1) << 20) | base] = H1;
}

__global__ __launch_bounds__(256) void st3d_kernel(
    const float* __restrict__ trans,
    float* __restrict__ out)
{
    int t = blockIdx.x * blockDim.x + threadIdx.x;

    int hs = t & 1;          // z-corner select: 0 -> z0, 1 -> z1
    int q  = t >> 1;         // voxel-pair index: voxels v0 = 2q, v0+1
    int v0 = q << 1;

    // v0 = ((b*128 + i)*128 + j)*128 + k0, k0 even -> pair shares b,i,j
    int k0 = v0 & 127;
    int j  = (v0 >> 7) & 127;
    int i  = (v0 >> 14) & 127;
    int b  = v0 >> 21;

    const float step = 2.0f / 127.0f;
    float xl  = -1.0f + (float)j * step;
    float yl  = -1.0f + (float)i * step;
    float zlA = -1.0f + (float)k0 * step;
    float zlB = zlA + step;

    // 6 transform floats for the voxel pair (streaming: don't pollute L2)
    const float2* tp = reinterpret_cast<const float2*>(trans) + (size_t)q * 3;
    float2 fa = __ldcs(&tp[0]);   // txA, tyA
    float2 fb = __ldcs(&tp[1]);   // tzA, txB
    float2 fc = __ldcs(&tp[2]);   // tyB, tzB

    // ---- voxel A setup ----
    float xA = 0.5f * (fa.x * xl + 1.0f) * 128.0f;
    float yA = 0.5f * (fa.y * yl + 1.0f) * 128.0f;
    float zA = 0.5f * (fb.x * zlA + 1.0f) * 128.0f;

    int x0A = min(max((int)floorf(xA), 0), 127);
    int y0A = (int)floorf(yA);
    int z0A = min(max((int)floorf(zA), 0), 127);
    int x1A = min(x0A + 1, 127);
    int y1A = min(max(y0A + 1, 0), 127);
    int z1A = min(z0A + 1, 127);
    y0A = min(max(y0A, 0), 127);

    float dxA = (float)x1A - xA, dyA = (float)y1A - yA, dzA = (float)z1A - zA;
    int   ziA = hs ? z1A : z0A;
    float wzA = hs ? (1.0f - dzA) : dzA;

    int baseA = (((b << 1) | (x0A & 1)) << 20) | ((x0A >> 1) << 7) | ziA;

    // ---- voxel B setup ----
    float xB = 0.5f * (fb.y * xl + 1.0f) * 128.0f;
    float yB = 0.5f * (fc.x * yl + 1.0f) * 128.0f;
    float zB = 0.5f * (fc.y * zlB + 1.0f) * 128.0f;

    int x0B = min(max((int)floorf(xB), 0), 127);
    int y0B = (int)floorf(yB);
    int z0B = min(max((int)floorf(zB), 0), 127);
    int x1B = min(x0B + 1, 127);
    int y1B = min(max(y0B + 1, 0), 127);
    int z1B = min(z0B + 1, 127);
    y0B = min(max(y0B, 0), 127);

    float dxB = (float)x1B - xB, dyB = (float)y1B - yB, dzB = (float)z1B - zB;
    int   ziB = hs ? z1B : z0B;
    float wzB = hs ? (1.0f - dzB) : dzB;

    int baseB = (((b << 1) | (x0B & 1)) << 20) | ((x0B >> 1) << 7) | ziB;

    // ---- issue all 4 gathers back-to-back (pair lanes share lines) ----
    uint4 hA0 = __ldg(&g_packed[baseA | (y0A << 13)]);
    uint4 hA1 = __ldg(&g_packed[baseA | (y1A << 13)]);
    uint4 hB0 = __ldg(&g_packed[baseB | (y0B << 13)]);
    uint4 hB1 = __ldg(&g_packed[baseB | (y1B << 13)]);

    float4 rA, rB;
    // ---- voxel A blend (this lane's z-corner) ----
    {
        float wy0 = wzA * dyA, wy1 = wzA * (1.0f - dyA);
        float ex  = 1.0f - dxA;

        float2 a0c01 = up2(hA0.x), a0c23 = up2(hA0.y);  // y0: x0 voxel
        float2 a1c01 = up2(hA0.z), a1c23 = up2(hA0.w);  // y0: x1 voxel
        float2 b0c01 = up2(hA1.x), b0c23 = up2(hA1.y);  // y1: x0 voxel
        float2 b1c01 = up2(hA1.z), b1c23 = up2(hA1.w);  // y1: x1 voxel

        rA.x = wy0 * (dxA * a0c01.x + ex * a1c01.x) + wy1 * (dxA * b0c01.x + ex * b1c01.x);
        rA.y = wy0 * (dxA * a0c01.y + ex * a1c01.y) + wy1 * (dxA * b0c01.y + ex * b1c01.y);
        rA.z = wy0 * (dxA * a0c23.x + ex * a1c23.x) + wy1 * (dxA * b0c23.x + ex * b1c23.x);
        rA.w = wy0 * (dxA * a0c23.y + ex * a1c23.y) + wy1 * (dxA * b0c23.y + ex * b1c23.y);
    }
    // ---- voxel B blend ----
    {
        float wy0 = wzB * dyB, wy1 = wzB * (1.0f - dyB);
        float ex  = 1.0f - dxB;

        float2 a0c01 = up2(hB0.x), a0c23 = up2(hB0.y);
        float2 a1c01 = up2(hB0.z), a1c23 = up2(hB0.w);
        float2 b0c01 = up2(hB1.x), b0c23 = up2(hB1.y);
        float2 b1c01 = up2(hB1.z), b1c23 = up2(hB1.w);

        rB.x = wy0 * (dxB * a0c01.x + ex * a1c01.x) + wy1 * (dxB * b0c01.x + ex * b1c01.x);
        rB.y = wy0 * (dxB * a0c01.y + ex * a1c01.y) + wy1 * (dxB * b0c01.y + ex * b1c01.y);
        rB.z = wy0 * (dxB * a0c23.x + ex * a1c23.x) + wy1 * (dxB * b0c23.x + ex * b1c23.x);
        rB.w = wy0 * (dxB * a0c23.y + ex * a1c23.y) + wy1 * (dxB * b0c23.y + ex * b1c23.y);
    }

    // combine z halves across the lane pair (both voxels)
    rA.x += __shfl_xor_sync(0xffffffffu, rA.x, 1);
    rA.y += __shfl_xor_sync(0xffffffffu, rA.y, 1);
    rA.z += __shfl_xor_sync(0xffffffffu, rA.z, 1);
    rA.w += __shfl_xor_sync(0xffffffffu, rA.w, 1);
    rB.x += __shfl_xor_sync(0xffffffffu, rB.x, 1);
    rB.y += __shfl_xor_sync(0xffffffffu, rB.y, 1);
    rB.z += __shfl_xor_sync(0xffffffffu, rB.z, 1);
    rB.w += __shfl_xor_sync(0xffffffffu, rB.w, 1);

    // even lane stores voxel v0, odd lane stores v0+1 -> dense streaming store
    float4 r = hs ? rB : rA;
    __stcs(reinterpret_cast<float4*>(out) + v0 + hs, r);
}

extern "C" void kernel_launch(void* const* d_in, const int* in_sizes, int n_in,
                              void* d_out, int out_size)
{
    const float* img = (const float*)d_in[0];
    const float* trans = (const float*)d_in[1];
    float* out = (float*)d_out;

    // prepass: 2 x-parity copies of fp16 x-pair patches (67MB, stays in L2)
    repack_kernel<<<2 * 128 * 64, 128>>>(reinterpret_cast<const float4*>(img));

    int total_threads = out_size / 4;
    st3d_kernel<<<total_threads / 256, 256>>>(trans, out);
}

// round 11
// speedup vs baseline: 1.1279x; 1.0354x over previous
#include <cuda_runtime.h>
#include <cuda_fp16.h>

// SpatialTransformer3D: batched 3D trilinear sampling.
//
// Prepass packs the image into fp16 x-pair patches, 2 parity copies:
//   patch(b,sx,y,px,z) = { img[y, 2px+sx, z], img[y, min(2px+sx+1,127), z] }
//   = 8 halves = 16B. Packed total 67MB (L2-scale working set).
// Main kernel: lane bit0 = z-corner select; pair lanes load patches at
// z0 / z0+1 (16B apart -> same 128B line) -> 2 distinct 128B lines per
// voxel (provably minimal for <=67MB packing). trans/out use streaming
// hints so the packed array keeps L2.
//
// image: (B=2, H=128, W=128, D=128, C=4) f32
// transformation: (B=2, 128, 128, 128, 3) f32
// out: (B=2, 128, 128, 128, 4) f32

__device__ uint4 g_packed[4 * 1048576];   // (b,sx) x (y,px,z), 67MB

__device__ __forceinline__ unsigned pack2(float a, float b) {
    __half2 h = __floats2half2_rn(a, b);
    return *reinterpret_cast<unsigned*>(&h);
}
__device__ __forceinline__ float2 up2(unsigned u) {
    __half2 h = *reinterpret_cast<__half2*>(&u);
    return __half22float2(h);
}

// one block per (b,y,px); 128 threads = z  (max-parallel structure; ~86% HBM)
__global__ __launch_bounds__(128) void repack_kernel(const float4* __restrict__ img)
{
    int z  = threadIdx.x;
    int bk = blockIdx.x;
    int px = bk & 63;
    int y  = (bk >> 6) & 127;
    int b  = bk >> 13;

    const float4* imgb = img + (size_t)b * 2097152;
    int x0 = 2 * px;

    // evict-first reads: don't let the f32 image displace packed in L2
    float4 v0 = __ldcs(&imgb[(y << 14) | (x0 << 7) | z]);
    float4 v1 = __ldcs(&imgb[(y << 14) | ((x0 + 1) << 7) | z]);
    float4 v2 = __ldcs(&imgb[(y << 14) | (min(x0 + 2, 127) << 7) | z]);

    uint4 H0, H1;
    H0.x = pack2(v0.x, v0.y);  H0.y = pack2(v0.z, v0.w);
    H0.z = pack2(v1.x, v1.y);  H0.w = pack2(v1.z, v1.w);
    H1.x = pack2(v1.x, v1.y);  H1.y = pack2(v1.z, v1.w);
    H1.z = pack2(v2.x, v2.y);  H1.w = pack2(v2.z, v2.w);

    int base = (y << 13) | (px << 7) | z;
    // default write-back stores: dirty lines stay resident in L2
    g_packed[(((b << 1) | 0) << 20) | base] = H0;
    g_packed[(((b << 1) | 1) << 20) | base] = H1;
}

__global__ __launch_bounds__(256) void st3d_kernel(
    const float* __restrict__ trans,
    float* __restrict__ out)
{
    int t = blockIdx.x * blockDim.x + threadIdx.x;

    int hs = t & 1;          // z-corner select: 0 -> z0, 1 -> z1
    int q  = t >> 1;         // voxel-pair index: voxels v0 = 2q, v0+1
    int v0 = q << 1;

    // v0 = ((b*128 + i)*128 + j)*128 + k0, k0 even -> pair shares b,i,j
    int k0 = v0 & 127;
    int j  = (v0 >> 7) & 127;
    int i  = (v0 >> 14) & 127;
    int b  = v0 >> 21;

    const float step = 2.0f / 127.0f;
    float xl  = -1.0f + (float)j * step;
    float yl  = -1.0f + (float)i * step;
    float zlA = -1.0f + (float)k0 * step;
    float zlB = zlA + step;

    // 6 transform floats for the voxel pair (streaming: don't pollute L2)
    const float2* tp = reinterpret_cast<const float2*>(trans) + (size_t)q * 3;
    float2 fa = __ldcs(&tp[0]);   // txA, tyA
    float2 fb = __ldcs(&tp[1]);   // tzA, txB
    float2 fc = __ldcs(&tp[2]);   // tyB, tzB

    // ---- voxel A setup ----
    float xA = 0.5f * (fa.x * xl + 1.0f) * 128.0f;
    float yA = 0.5f * (fa.y * yl + 1.0f) * 128.0f;
    float zA = 0.5f * (fb.x * zlA + 1.0f) * 128.0f;

    int x0A = min(max((int)floorf(xA), 0), 127);
    int y0A = (int)floorf(yA);
    int z0A = min(max((int)floorf(zA), 0), 127);
    int x1A = min(x0A + 1, 127);
    int y1A = min(max(y0A + 1, 0), 127);
    int z1A = min(z0A + 1, 127);
    y0A = min(max(y0A, 0), 127);

    float dxA = (float)x1A - xA, dyA = (float)y1A - yA, dzA = (float)z1A - zA;
    int   ziA = hs ? z1A : z0A;
    float wzA = hs ? (1.0f - dzA) : dzA;

    int baseA = (((b << 1) | (x0A & 1)) << 20) | ((x0A >> 1) << 7) | ziA;

    // ---- voxel B setup ----
    float xB = 0.5f * (fb.y * xl + 1.0f) * 128.0f;
    float yB = 0.5f * (fc.x * yl + 1.0f) * 128.0f;
    float zB = 0.5f * (fc.y * zlB + 1.0f) * 128.0f;

    int x0B = min(max((int)floorf(xB), 0), 127);
    int y0B = (int)floorf(yB);
    int z0B = min(max((int)floorf(zB), 0), 127);
    int x1B = min(x0B + 1, 127);
    int y1B = min(max(y0B + 1, 0), 127);
    int z1B = min(z0B + 1, 127);
    y0B = min(max(y0B, 0), 127);

    float dxB = (float)x1B - xB, dyB = (float)y1B - yB, dzB = (float)z1B - zB;
    int   ziB = hs ? z1B : z0B;
    float wzB = hs ? (1.0f - dzB) : dzB;

    int baseB = (((b << 1) | (x0B & 1)) << 20) | ((x0B >> 1) << 7) | ziB;

    // ---- issue all 4 gathers back-to-back (pair lanes share lines) ----
    uint4 hA0 = g_packed[baseA | (y0A << 13)];
    uint4 hA1 = g_packed[baseA | (y1A << 13)];
    uint4 hB0 = g_packed[baseB | (y0B << 13)];
    uint4 hB1 = g_packed[baseB | (y1B << 13)];

    float4 rA, rB;
    // ---- voxel A blend (this lane's z-corner) ----
    {
        float wy0 = wzA * dyA, wy1 = wzA * (1.0f - dyA);
        float ex  = 1.0f - dxA;

        float2 a0c01 = up2(hA0.x), a0c23 = up2(hA0.y);  // y0: x0 voxel
        float2 a1c01 = up2(hA0.z), a1c23 = up2(hA0.w);  // y0: x1 voxel
        float2 b0c01 = up2(hA1.x), b0c23 = up2(hA1.y);  // y1: x0 voxel
        float2 b1c01 = up2(hA1.z), b1c23 = up2(hA1.w);  // y1: x1 voxel

        rA.x = wy0 * (dxA * a0c01.x + ex * a1c01.x) + wy1 * (dxA * b0c01.x + ex * b1c01.x);
        rA.y = wy0 * (dxA * a0c01.y + ex * a1c01.y) + wy1 * (dxA * b0c01.y + ex * b1c01.y);
        rA.z = wy0 * (dxA * a0c23.x + ex * a1c23.x) + wy1 * (dxA * b0c23.x + ex * b1c23.x);
        rA.w = wy0 * (dxA * a0c23.y + ex * a1c23.y) + wy1 * (dxA * b0c23.y + ex * b1c23.y);
    }
    // ---- voxel B blend ----
    {
        float wy0 = wzB * dyB, wy1 = wzB * (1.0f - dyB);
        float ex  = 1.0f - dxB;

        float2 a0c01 = up2(hB0.x), a0c23 = up2(hB0.y);
        float2 a1c01 = up2(hB0.z), a1c23 = up2(hB0.w);
        float2 b0c01 = up2(hB1.x), b0c23 = up2(hB1.y);
        float2 b1c01 = up2(hB1.z), b1c23 = up2(hB1.w);

        rB.x = wy0 * (dxB * a0c01.x + ex * a1c01.x) + wy1 * (dxB * b0c01.x + ex * b1c01.x);
        rB.y = wy0 * (dxB * a0c01.y + ex * a1c01.y) + wy1 * (dxB * b0c01.y + ex * b1c01.y);
        rB.z = wy0 * (dxB * a0c23.x + ex * a1c23.x) + wy1 * (dxB * b0c23.x + ex * b1c23.x);
        rB.w = wy0 * (dxB * a0c23.y + ex * a1c23.y) + wy1 * (dxB * b0c23.y + ex * b1c23.y);
    }

    // combine z halves across the lane pair (both voxels)
    rA.x += __shfl_xor_sync(0xffffffffu, rA.x, 1);
    rA.y += __shfl_xor_sync(0xffffffffu, rA.y, 1);
    rA.z += __shfl_xor_sync(0xffffffffu, rA.z, 1);
    rA.w += __shfl_xor_sync(0xffffffffu, rA.w, 1);
    rB.x += __shfl_xor_sync(0xffffffffu, rB.x, 1);
    rB.y += __shfl_xor_sync(0xffffffffu, rB.y, 1);
    rB.z += __shfl_xor_sync(0xffffffffu, rB.z, 1);
    rB.w += __shfl_xor_sync(0xffffffffu, rB.w, 1);

    // even lane stores voxel v0, odd lane stores v0+1 -> dense streaming store
    float4 r = hs ? rB : rA;
    __stcs(reinterpret_cast<float4*>(out) + v0 + hs, r);
}

extern "C" void kernel_launch(void* const* d_in, const int* in_sizes, int n_in,
                              void* d_out, int out_size)
{
    const float* img = (const float*)d_in[0];
    const float* trans = (const float*)d_in[1];
    float* out = (float*)d_out;

    // prepass: 2 x-parity copies of fp16 x-pair patches (67MB)
    repack_kernel<<<2 * 128 * 64, 128>>>(reinterpret_cast<const float4*>(img));

    int total_threads = out_size / 4;
    st3d_kernel<<<total_threads / 256, 256>>>(trans, out);
}